// round 16
// baseline (speedup 1.0000x reference)
#include <cuda_runtime.h>
#include <cuda_fp16.h>
#include <math.h>
#include <stdint.h>

// Problem constants
#define BB 4
#define NN 2048
#define DD 1024
#define HH 8
#define HDIM 128
#define MM (BB*NN)     // 8192 rows
#define TCH 256        // sequence chunk length
#define NCHUNK 8       // NN / TCH

// Scratch (allocation-free rule: __device__ globals)
__device__ float  g_q[(size_t)MM*DD];
__device__ float  g_k[(size_t)MM*DD];
__device__ float  g_g[(size_t)MM*DD];
__device__ float  g_v[(size_t)MM*DD];
__device__ float  g_p0[(size_t)MM*DD];
__device__ float  g_state[128*256*16];       // scan state between chunks
__device__ __half g_hx[(size_t)MM*DD];       // x in fp16
__device__ __half g_hw[4*(size_t)DD*DD];     // weights in fp16
__device__ __half g_hnrm[(size_t)MM*DD];     // rmsnorm output in fp16

// ---------------------------------------------------------------------------
// helpers
// ---------------------------------------------------------------------------
__device__ __forceinline__ void mma_fp16(float c[4], const uint32_t a[4],
                                         uint32_t b0, uint32_t b1) {
    asm volatile(
        "mma.sync.aligned.m16n8k16.row.col.f32.f16.f16.f32 "
        "{%0,%1,%2,%3},{%4,%5,%6,%7},{%8,%9},{%0,%1,%2,%3};"
        : "+f"(c[0]), "+f"(c[1]), "+f"(c[2]), "+f"(c[3])
        : "r"(a[0]), "r"(a[1]), "r"(a[2]), "r"(a[3]), "r"(b0), "r"(b1));
}

__device__ __forceinline__ void ldm_x4(uint32_t r[4], uint32_t addr) {
    asm volatile(
        "ldmatrix.sync.aligned.m8n8.x4.shared.b16 {%0,%1,%2,%3}, [%4];"
        : "=r"(r[0]), "=r"(r[1]), "=r"(r[2]), "=r"(r[3]) : "r"(addr));
}

__device__ __forceinline__ void cp16(uint32_t dst, const void* src) {
    asm volatile("cp.async.cg.shared.global [%0], [%1], 16;"
                 :: "r"(dst), "l"(src));
}

__device__ __forceinline__ uint32_t s2u(const void* p) {
    uint32_t a;
    asm("{ .reg .u64 t; cvta.to.shared.u64 t, %1; cvt.u32.u64 %0, t; }"
        : "=r"(a) : "l"(p));
    return a;
}

// ---------------------------------------------------------------------------
// Conversion constants
// ---------------------------------------------------------------------------
#define N4W (DD * DD / 4)            // 262144 float4 per weight
#define N4CH (BB * TCH * DD / 4)     // 262144 float4 per x time-chunk
#define N4PB (TCH * DD / 4)          // 65536 float4 per batch per chunk

// L0 kernel: convert 4 weights + x chunk 0
__global__ __launch_bounds__(256)
void cvt0_kernel(const float4* __restrict__ x,
                 const float4* __restrict__ wq, const float4* __restrict__ wk,
                 const float4* __restrict__ wv, const float4* __restrict__ wo,
                 __half2* __restrict__ hx, __half2* __restrict__ hw)
{
    int i = blockIdx.x * blockDim.x + threadIdx.x;
    if (i >= 4 * N4W + N4CH) return;
    const float4* src;
    __half2* dst;
    size_t r;
    if (i < 4 * N4W) {
        int w = i / N4W;
        r = i - w * N4W;
        src = (w == 0) ? wq : (w == 1) ? wk : (w == 2) ? wv : wo;
        dst = hw + (size_t)w * N4W * 2;
    } else {
        int j = i - 4 * N4W;               // 0..N4CH-1, x chunk 0
        int b = j >> 16;                   // / N4PB
        int rem = j & (N4PB - 1);
        r = (size_t)b * (NN * DD / 4) + rem;
        src = x;
        dst = hx;
    }
    float4 v = src[r];
    dst[2*r]   = __floats2half2_rn(v.x, v.y);
    dst[2*r+1] = __floats2half2_rn(v.z, v.w);
}

// ---------------------------------------------------------------------------
// HMMA GEMM tile: C[bm:+128, bn:+128] = epi( A @ W^T ). BK=64 halves,
// 8 warps 4x2, warp tile 32x64, ldmatrix.x4, cp.async double buffer.
// ---------------------------------------------------------------------------
#define RS 72
#define ABUF_BYTES (128 * RS * 2)
#define BREG_BYTES (2 * ABUF_BYTES)
#define GEMM_SMEM_BYTES (4 * ABUF_BYTES)   // 73728

__device__ __forceinline__
void gemm_tile(const __half* __restrict__ A, const __half* __restrict__ W,
               float* __restrict__ C, float* __restrict__ C2,
               int bm, int bn, int mode, uint32_t sb)
{
    const int K = DD, Nc = DD;
    const int t  = threadIdx.x;
    const int warp = t >> 5, lane = t & 31;
    const int wm = (warp >> 1) * 32;
    const int wn = (warp & 1) * 64;
    const int qrow = lane >> 2;
    const int qcol = lane & 3;

    float acc[2][8][4];
    #pragma unroll
    for (int mt = 0; mt < 2; mt++)
        #pragma unroll
        for (int nt = 0; nt < 8; nt++)
            #pragma unroll
            for (int i = 0; i < 4; i++) acc[mt][nt][i] = 0.f;

    int rowv[4], segv[4];
    #pragma unroll
    for (int r = 0; r < 4; r++) {
        int idx = t + r * 256;
        rowv[r] = idx >> 3;
        segv[r] = idx & 7;
    }

    const int lgrp = lane >> 3, lrow = lane & 7;
    uint32_t aoffb[2], boffb[4];
    #pragma unroll
    for (int mt = 0; mt < 2; mt++) {
        int row = wm + mt * 16 + (lgrp & 1) * 8 + lrow;
        aoffb[mt] = (uint32_t)(row * RS + (lgrp >> 1) * 8) * 2;
    }
    #pragma unroll
    for (int p = 0; p < 4; p++) {
        int row = wn + p * 16 + (lgrp >> 1) * 8 + lrow;
        boffb[p] = (uint32_t)(row * RS + (lgrp & 1) * 8) * 2 + BREG_BYTES;
    }

    #pragma unroll
    for (int r = 0; r < 4; r++) {
        uint32_t so = (uint32_t)(rowv[r] * RS + segv[r] * 8) * 2;
        cp16(sb + so,              &A[(size_t)(bm + rowv[r]) * K + segv[r] * 8]);
        cp16(sb + BREG_BYTES + so, &W[(size_t)(bn + rowv[r]) * K + segv[r] * 8]);
    }
    asm volatile("cp.async.commit_group;" ::: "memory");

    const int NCH = K / 64;
    #pragma unroll 1
    for (int ch = 0; ch < NCH; ch++) {
        const uint32_t bufB = (uint32_t)(ch & 1) * ABUF_BYTES;
        if (ch + 1 < NCH) {
            const uint32_t nbufB = (uint32_t)((ch + 1) & 1) * ABUF_BYTES;
            const int k0n = (ch + 1) * 64;
            #pragma unroll
            for (int r = 0; r < 4; r++) {
                uint32_t so = (uint32_t)(rowv[r] * RS + segv[r] * 8) * 2;
                cp16(sb + nbufB + so,
                     &A[(size_t)(bm + rowv[r]) * K + k0n + segv[r] * 8]);
                cp16(sb + BREG_BYTES + nbufB + so,
                     &W[(size_t)(bn + rowv[r]) * K + k0n + segv[r] * 8]);
            }
            asm volatile("cp.async.commit_group;" ::: "memory");
            asm volatile("cp.async.wait_group 1;" ::: "memory");
        } else {
            asm volatile("cp.async.wait_group 0;" ::: "memory");
        }
        __syncthreads();

        #pragma unroll
        for (int ks = 0; ks < 4; ks++) {
            const uint32_t kb = sb + bufB + (uint32_t)ks * 32;
            uint32_t a0[4], a1[4];
            ldm_x4(a0, kb + aoffb[0]);
            ldm_x4(a1, kb + aoffb[1]);
            #pragma unroll
            for (int p = 0; p < 4; p++) {
                uint32_t bb[4];
                ldm_x4(bb, kb + boffb[p]);
                mma_fp16(acc[0][2*p],   a0, bb[0], bb[1]);
                mma_fp16(acc[1][2*p],   a1, bb[0], bb[1]);
                mma_fp16(acc[0][2*p+1], a0, bb[2], bb[3]);
                mma_fp16(acc[1][2*p+1], a1, bb[2], bb[3]);
            }
        }
        __syncthreads();
    }

    #pragma unroll
    for (int mt = 0; mt < 2; mt++) {
        #pragma unroll
        for (int nt = 0; nt < 8; nt++) {
            int row = bm + wm + mt * 16 + qrow;
            int col = bn + wn + nt * 8 + qcol * 2;
            #pragma unroll
            for (int half = 0; half < 2; half++) {
                int r = row + half * 8;
                float z0 = acc[mt][nt][half * 2 + 0];
                float z1 = acc[mt][nt][half * 2 + 1];
                if (mode == 0) {
                    float s0 = 1.f / (1.f + __expf(-z0));
                    float s1 = 1.f / (1.f + __expf(-z1));
                    float2 o = make_float2(z0 * s0, z1 * s1);
                    *reinterpret_cast<float2*>(&C[(size_t)r * Nc + col]) = o;
                } else if (mode == 1) {
                    float f0 = 1.f / (1.f + __expf(-z0));
                    float f1 = 1.f / (1.f + __expf(-z1));
                    float2 kk2 = make_float2(1.f - f0, 1.f - f1);
                    float2 gg2 = make_float2(-log1pf(__expf(-f0)),
                                             -log1pf(__expf(-f1)));
                    *reinterpret_cast<float2*>(&C [(size_t)r * Nc + col]) = kk2;
                    *reinterpret_cast<float2*>(&C2[(size_t)r * Nc + col]) = gg2;
                } else {
                    float2 o = make_float2(z0, z1);
                    *reinterpret_cast<float2*>(&C[(size_t)r * Nc + col]) = o;
                }
            }
        }
    }
}

// ---------------------------------------------------------------------------
// Scan role v6: 128 CTAs; CTA = one (bh, dvb): 32 dv x full dk=128.
// 256 threads: thread = (dv_local = t>>3, dkq = t&7), S[16] per thread
// (float4 groups fi = j*8 + dkq, j=0..3). CTA-wide q/k/e staging (t<128
// loads), one __syncthreads per step. Writes COMPLETE outputs to P0.
// ---------------------------------------------------------------------------
__device__ __forceinline__
void scan_role(int cta, int cs,
               const float* __restrict__ Q, const float* __restrict__ Kk,
               const float* __restrict__ G, const float* __restrict__ V,
               float* __restrict__ P0, float* __restrict__ ST, float* smemf)
{
    const int t = threadIdx.x;
    const int bh  = cta & 31;
    const int dvb = cta >> 5;              // 0..3
    const int b = bh >> 3, h = bh & 7;
    const int dv_local = t >> 3;           // 0..31
    const int dkq      = t & 7;            // 0..7
    const int vcol = dvb * 32 + dv_local;

    const size_t gbase = (size_t)b * NN * DD + (size_t)h * HDIM;

    float S[16];
    if (cs == 0) {
        #pragma unroll
        for (int i = 0; i < 16; i++) S[i] = 0.f;
    } else {
        #pragma unroll
        for (int i = 0; i < 16; i++)
            S[i] = ST[((size_t)cta * 256 + t) * 16 + i];
    }

    size_t off = gbase + (size_t)(cs * TCH) * DD;
    float r0 = 0.f, r1 = 0.f, r2 = 0.f;
    if (t < 128) {
        r0 = Q [off + t];
        r1 = Kk[off + t];
        r2 = G [off + t];
    }
    float rv = V[off + vcol];

    #pragma unroll 1
    for (int tstep = 0; tstep < TCH; tstep++) {
        const int bufo = (tstep & 1) * 384;   // q[128], k[128], e[128]
        if (t < 128) {
            smemf[bufo + t]       = r0;
            smemf[bufo + 128 + t] = r1;
            smemf[bufo + 256 + t] = __expf(r2);
        }
        const float vv = rv;

        const size_t noff = off + DD;
        if (tstep + 1 < TCH) {
            if (t < 128) {
                r0 = Q [noff + t];
                r1 = Kk[noff + t];
                r2 = G [noff + t];
            }
            rv = V[noff + vcol];
        }
        __syncthreads();

        const float4* q4 = reinterpret_cast<const float4*>(smemf + bufo);
        const float4* k4 = reinterpret_cast<const float4*>(smemf + bufo + 128);
        const float4* e4 = reinterpret_cast<const float4*>(smemf + bufo + 256);

        float oacc = 0.f;
        #pragma unroll
        for (int j = 0; j < 4; j++) {
            const int fi = j * 8 + dkq;
            float4 qa = q4[fi], ka = k4[fi], ea = e4[fi];
            float s;
            s = fmaf(ea.x, S[4*j+0], ka.x * vv); S[4*j+0] = s; oacc = fmaf(qa.x, s, oacc);
            s = fmaf(ea.y, S[4*j+1], ka.y * vv); S[4*j+1] = s; oacc = fmaf(qa.y, s, oacc);
            s = fmaf(ea.z, S[4*j+2], ka.z * vv); S[4*j+2] = s; oacc = fmaf(qa.z, s, oacc);
            s = fmaf(ea.w, S[4*j+3], ka.w * vv); S[4*j+3] = s; oacc = fmaf(qa.w, s, oacc);
        }
        // reduce over the 8 dkq lanes (adjacent in warp)
        oacc += __shfl_xor_sync(0xffffffffu, oacc, 1);
        oacc += __shfl_xor_sync(0xffffffffu, oacc, 2);
        oacc += __shfl_xor_sync(0xffffffffu, oacc, 4);
        if (dkq == 0) P0[off + vcol] = oacc;

        off = noff;
    }

    if (cs < NCHUNK - 1) {
        #pragma unroll
        for (int i = 0; i < 16; i++)
            ST[((size_t)cta * 256 + t) * 16 + i] = S[i];
    }
}

// ---------------------------------------------------------------------------
// RMSNorm role: 16 rows per CTA (64 CTAs), single input buffer.
// Chunk cr: ci = cta*16+r in [0,1024): b = ci>>8, row = b*NN+cr*TCH+(ci&255).
// ---------------------------------------------------------------------------
__device__ __forceinline__
void rms_role(int cta, int cr,
              const float* __restrict__ X0,
              const float* __restrict__ w, __half2* __restrict__ Y,
              float* smemf)
{
    float* red = smemf;
    const int t = threadIdx.x;

    #pragma unroll 1
    for (int r = 0; r < 16; r++) {
        const int ci  = cta * 16 + r;                    // 0..1023
        const int row = (ci >> 8) * NN + cr * TCH + (ci & (TCH - 1));
        const size_t idx = (size_t)row * DD + t * 4;

        float4 xv = *reinterpret_cast<const float4*>(&X0[idx]);

        float ss = xv.x*xv.x + xv.y*xv.y + xv.z*xv.z + xv.w*xv.w;
        #pragma unroll
        for (int o = 16; o; o >>= 1) ss += __shfl_xor_sync(0xffffffffu, ss, o);
        if ((t & 31) == 0) red[t >> 5] = ss;
        __syncthreads();
        if (t < 8) {
            float x = red[t];
            #pragma unroll
            for (int o = 4; o; o >>= 1) x += __shfl_xor_sync(0xffu, x, o);
            if (t == 0) red[0] = x;
        }
        __syncthreads();
        float inv = rsqrtf(red[0] * (1.f / DD) + 1e-6f);

        float4 wv = *reinterpret_cast<const float4*>(&w[t * 4]);
        size_t o2 = (size_t)row * (DD/2) + t * 2;
        Y[o2]   = __floats2half2_rn(xv.x * inv * wv.x, xv.y * inv * wv.y);
        Y[o2+1] = __floats2half2_rn(xv.z * inv * wv.z, xv.w * inv * wv.w);
        __syncthreads();
    }
}

// ---------------------------------------------------------------------------
// cvtx role: convert x time-chunk ccv to fp16. 64 CTAs x 256 thr x 16 float4.
// ---------------------------------------------------------------------------
__device__ __forceinline__
void cvtx_role(int cta, int ccv, const float4* __restrict__ x,
               __half2* __restrict__ hx)
{
    int tid = cta * 256 + threadIdx.x;     // 0..16383
    #pragma unroll 1
    for (int it = 0; it < 16; it++) {
        int j = tid + it * 16384;          // 0..N4CH-1
        int b = j >> 16;                   // / N4PB
        int rem = j & (N4PB - 1);
        size_t r = (size_t)b * (NN * DD / 4) + (size_t)ccv * N4PB + rem;
        float4 v = x[r];
        hx[2*r]   = __floats2half2_rn(v.x, v.y);
        hx[2*r+1] = __floats2half2_rn(v.z, v.w);
    }
}

// ---------------------------------------------------------------------------
// Time-chunk GEMM m-tile mapping. TCH=256 => 2 m-tiles per batch per chunk.
// ---------------------------------------------------------------------------
__device__ __forceinline__ int chunk_bm(int c, int mt) {
    return (mt >> 1) * NN + c * TCH + (mt & 1) * 128;
}

// ---------------------------------------------------------------------------
// Mega kernel. Bid order seeds wave 1 with both scan AND GEMM:
// [scan(128) | QKV-A(128) | rms(64) | cvtx(64) | O(64) | QKV-B(64)]
// ---------------------------------------------------------------------------
__global__ __launch_bounds__(256, 2)
void mega_kernel(const float4* __restrict__ xf, const __half* __restrict__ hx,
                 const __half* __restrict__ hw,
                 float* __restrict__ pq, float* __restrict__ pk,
                 float* __restrict__ pg, float* __restrict__ pv,
                 float* __restrict__ p0,
                 float* __restrict__ pstate, __half* __restrict__ hnrm,
                 const float* __restrict__ norm_w, float* __restrict__ outp,
                 int n_scan, int cs, int n_qa, int n_rms, int cr,
                 int n_cvt, int ccv, int n_o, int co, int n_qb, int cq)
{
    extern __shared__ __align__(16) __half smem_raw[];
    int bid = blockIdx.x;

    if (bid < n_scan) {
        scan_role(bid, cs, pq, pk, pg, pv, p0, pstate,
                  reinterpret_cast<float*>(smem_raw));
        return;
    }
    bid -= n_scan;
    if (bid < n_qa) {
        // QKV tiles 0..127
        int which = bid >> 6;
        int tile  = bid & 63;
        int mt = tile >> 3, nt = tile & 7;
        const __half* Wp = hw + (size_t)which * DD * DD;
        float* C  = (which == 0) ? pq : (which == 1) ? pk : pv;
        float* C2 = (which == 1) ? pg : nullptr;
        gemm_tile(hx, Wp, C, C2, chunk_bm(cq, mt), nt * 128, which,
                  s2u(smem_raw));
        return;
    }
    bid -= n_qa;
    if (bid < n_rms) {
        rms_role(bid, cr, p0, norm_w,
                 reinterpret_cast<__half2*>(hnrm),
                 reinterpret_cast<float*>(smem_raw));
        return;
    }
    bid -= n_rms;
    if (bid < n_cvt) {
        cvtx_role(bid, ccv, xf, (__half2*)hx);
        return;
    }
    bid -= n_cvt;
    if (bid < n_o) {
        int mt = bid >> 3, nt = bid & 7;     // 64 tiles
        gemm_tile(hnrm, hw + 3*(size_t)DD*DD, outp, nullptr,
                  chunk_bm(co, mt), nt * 128, 2, s2u(smem_raw));
        return;
    }
    bid -= n_o;
    {
        // QKV tiles 128..191
        int qi = 128 + bid;
        int which = qi >> 6;
        int tile  = qi & 63;
        int mt = tile >> 3, nt = tile & 7;
        const __half* Wp = hw + (size_t)which * DD * DD;
        float* C  = (which == 0) ? pq : (which == 1) ? pk : pv;
        float* C2 = (which == 1) ? pg : nullptr;
        gemm_tile(hx, Wp, C, C2, chunk_bm(cq, mt), nt * 128, which,
                  s2u(smem_raw));
    }
}

// ---------------------------------------------------------------------------
extern "C" void kernel_launch(void* const* d_in, const int* in_sizes, int n_in,
                              void* d_out, int out_size)
{
    const float* x      = (const float*)d_in[0];
    const float* Wq     = (const float*)d_in[1];
    const float* Wk     = (const float*)d_in[2];
    const float* Wv     = (const float*)d_in[3];
    const float* Wo     = (const float*)d_in[4];
    const float* norm_w = (const float*)d_in[5];
    float* out = (float*)d_out;

    float *pq, *pk, *pg, *pv, *p0, *pstate;
    __half *phx, *phw, *phnrm;
    cudaGetSymbolAddress((void**)&pq,     g_q);
    cudaGetSymbolAddress((void**)&pk,     g_k);
    cudaGetSymbolAddress((void**)&pg,     g_g);
    cudaGetSymbolAddress((void**)&pv,     g_v);
    cudaGetSymbolAddress((void**)&p0,     g_p0);
    cudaGetSymbolAddress((void**)&pstate, g_state);
    cudaGetSymbolAddress((void**)&phx,    g_hx);
    cudaGetSymbolAddress((void**)&phw,    g_hw);
    cudaGetSymbolAddress((void**)&phnrm,  g_hnrm);

    // L0: convert the 4 weights + x time-chunk 0 (~8 us)
    const int n0 = 4 * N4W + N4CH;
    cvt0_kernel<<<(n0 + 255) / 256, 256>>>(
        (const float4*)x, (const float4*)Wq, (const float4*)Wk,
        (const float4*)Wv, (const float4*)Wo,
        (__half2*)phx, (__half2*)phw);

    cudaFuncSetAttribute(mega_kernel,
        cudaFuncAttributeMaxDynamicSharedMemorySize, GEMM_SMEM_BYTES);

    #define LAUNCH(nsc, csv, nqa, nrm, crv, ncv, ccv, no, cov, nqb, cqv)         \
        mega_kernel<<<(nsc)+(nqa)+(nrm)+(ncv)+(no)+(nqb), 256,                   \
                      GEMM_SMEM_BYTES>>>(                                        \
            (const float4*)x, phx, phw, pq, pk, pg, pv, p0,                      \
            pstate, phnrm, norm_w, out,                                          \
            (nsc), (csv), (nqa), (nrm), (crv), (ncv), (ccv),                     \
            (no), (cov), (nqb), (cqv))

    // 8-chunk pipeline; cvtx(k) one launch ahead of QKV(k).
    // Roles: scan=128, QKV-A=128, rms=64, cvtx=64, O=64, QKV-B=64 CTAs.
    LAUNCH(  0, 0, 128,  0, 0, 64, 1,  0, 0, 64, 0);   // QKV(0), cvtx(1)
    LAUNCH(128, 0, 128,  0, 0, 64, 2,  0, 0, 64, 1);   // scan(0) QKV(1) cvtx(2)
    LAUNCH(128, 1, 128, 64, 0, 64, 3,  0, 0, 64, 2);   // + rms(0)
    LAUNCH(128, 2, 128, 64, 1, 64, 4, 64, 0, 64, 3);   // + O(0)
    LAUNCH(128, 3, 128, 64, 2, 64, 5, 64, 1, 64, 4);
    LAUNCH(128, 4, 128, 64, 3, 64, 6, 64, 2, 64, 5);
    LAUNCH(128, 5, 128, 64, 4, 64, 7, 64, 3, 64, 6);
    LAUNCH(128, 6, 128, 64, 5,  0, 0, 64, 4, 64, 7);
    LAUNCH(128, 7,   0, 64, 6,  0, 0, 64, 5,  0, 0);   // scan(7) rms(6) O(5)
    LAUNCH(  0, 0,   0, 64, 7,  0, 0, 64, 6,  0, 0);   //         rms(7) O(6)
    LAUNCH(  0, 0,   0,  0, 0,  0, 0, 64, 7,  0, 0);   //                O(7)
    #undef LAUNCH
}

// round 17
// speedup vs baseline: 1.3094x; 1.3094x over previous
#include <cuda_runtime.h>
#include <cuda_fp16.h>
#include <math.h>
#include <stdint.h>

// Problem constants
#define BB 4
#define NN 2048
#define DD 1024
#define HH 8
#define HDIM 128
#define MM (BB*NN)     // 8192 rows
#define TCH 256        // sequence chunk length
#define NCHUNK 8       // NN / TCH

// Scratch (allocation-free rule: __device__ globals)
__device__ float  g_q[(size_t)MM*DD];
__device__ float  g_k[(size_t)MM*DD];
__device__ float  g_g[(size_t)MM*DD];
__device__ float  g_v[(size_t)MM*DD];
__device__ float  g_p0[(size_t)MM*DD];
__device__ float  g_p1[(size_t)MM*DD];
__device__ float  g_p2[(size_t)MM*DD];
__device__ float  g_p3[(size_t)MM*DD];
__device__ float  g_state[512*128*8];        // scan state between chunks
__device__ __half g_hx[(size_t)MM*DD];       // x in fp16
__device__ __half g_hw[4*(size_t)DD*DD];     // weights in fp16
__device__ __half g_hnrm[(size_t)MM*DD];     // rmsnorm output in fp16

// ---------------------------------------------------------------------------
// helpers
// ---------------------------------------------------------------------------
__device__ __forceinline__ void mma_fp16(float c[4], const uint32_t a[4],
                                         uint32_t b0, uint32_t b1) {
    asm volatile(
        "mma.sync.aligned.m16n8k16.row.col.f32.f16.f16.f32 "
        "{%0,%1,%2,%3},{%4,%5,%6,%7},{%8,%9},{%0,%1,%2,%3};"
        : "+f"(c[0]), "+f"(c[1]), "+f"(c[2]), "+f"(c[3])
        : "r"(a[0]), "r"(a[1]), "r"(a[2]), "r"(a[3]), "r"(b0), "r"(b1));
}

__device__ __forceinline__ void ldm_x4(uint32_t r[4], uint32_t addr) {
    asm volatile(
        "ldmatrix.sync.aligned.m8n8.x4.shared.b16 {%0,%1,%2,%3}, [%4];"
        : "=r"(r[0]), "=r"(r[1]), "=r"(r[2]), "=r"(r[3]) : "r"(addr));
}

__device__ __forceinline__ void cp16(uint32_t dst, const void* src) {
    asm volatile("cp.async.cg.shared.global [%0], [%1], 16;"
                 :: "r"(dst), "l"(src));
}

__device__ __forceinline__ uint32_t s2u(const void* p) {
    uint32_t a;
    asm("{ .reg .u64 t; cvta.to.shared.u64 t, %1; cvt.u32.u64 %0, t; }"
        : "=r"(a) : "l"(p));
    return a;
}

// ---------------------------------------------------------------------------
// Conversion constants
// ---------------------------------------------------------------------------
#define N4W (DD * DD / 4)            // 262144 float4 per weight
#define N4CH (BB * TCH * DD / 4)     // 262144 float4 per x time-chunk
#define N4PB (TCH * DD / 4)          // 65536 float4 per batch per chunk

// L0 kernel: convert 4 weights + x chunk 0
__global__ __launch_bounds__(256)
void cvt0_kernel(const float4* __restrict__ x,
                 const float4* __restrict__ wq, const float4* __restrict__ wk,
                 const float4* __restrict__ wv, const float4* __restrict__ wo,
                 __half2* __restrict__ hx, __half2* __restrict__ hw)
{
    int i = blockIdx.x * blockDim.x + threadIdx.x;
    if (i >= 4 * N4W + N4CH) return;
    const float4* src;
    __half2* dst;
    size_t r;
    if (i < 4 * N4W) {
        int w = i / N4W;
        r = i - w * N4W;
        src = (w == 0) ? wq : (w == 1) ? wk : (w == 2) ? wv : wo;
        dst = hw + (size_t)w * N4W * 2;
    } else {
        int j = i - 4 * N4W;               // 0..N4CH-1, x chunk 0
        int b = j >> 16;                   // / N4PB
        int rem = j & (N4PB - 1);
        r = (size_t)b * (NN * DD / 4) + rem;
        src = x;
        dst = hx;
    }
    float4 v = src[r];
    dst[2*r]   = __floats2half2_rn(v.x, v.y);
    dst[2*r+1] = __floats2half2_rn(v.z, v.w);
}

// ---------------------------------------------------------------------------
// HMMA GEMM tile: C[bm:+128, bn:+128] = epi( A @ W^T ). BK=64 halves,
// 8 warps 4x2, warp tile 32x64, ldmatrix.x4, cp.async double buffer.
// ---------------------------------------------------------------------------
#define RS 72
#define ABUF_BYTES (128 * RS * 2)
#define BREG_BYTES (2 * ABUF_BYTES)
#define GEMM_SMEM_BYTES (4 * ABUF_BYTES)   // 73728

__device__ __forceinline__
void gemm_tile(const __half* __restrict__ A, const __half* __restrict__ W,
               float* __restrict__ C, float* __restrict__ C2,
               int bm, int bn, int mode, uint32_t sb)
{
    const int K = DD, Nc = DD;
    const int t  = threadIdx.x;
    const int warp = t >> 5, lane = t & 31;
    const int wm = (warp >> 1) * 32;
    const int wn = (warp & 1) * 64;
    const int qrow = lane >> 2;
    const int qcol = lane & 3;

    float acc[2][8][4];
    #pragma unroll
    for (int mt = 0; mt < 2; mt++)
        #pragma unroll
        for (int nt = 0; nt < 8; nt++)
            #pragma unroll
            for (int i = 0; i < 4; i++) acc[mt][nt][i] = 0.f;

    int rowv[4], segv[4];
    #pragma unroll
    for (int r = 0; r < 4; r++) {
        int idx = t + r * 256;
        rowv[r] = idx >> 3;
        segv[r] = idx & 7;
    }

    const int lgrp = lane >> 3, lrow = lane & 7;
    uint32_t aoffb[2], boffb[4];
    #pragma unroll
    for (int mt = 0; mt < 2; mt++) {
        int row = wm + mt * 16 + (lgrp & 1) * 8 + lrow;
        aoffb[mt] = (uint32_t)(row * RS + (lgrp >> 1) * 8) * 2;
    }
    #pragma unroll
    for (int p = 0; p < 4; p++) {
        int row = wn + p * 16 + (lgrp >> 1) * 8 + lrow;
        boffb[p] = (uint32_t)(row * RS + (lgrp & 1) * 8) * 2 + BREG_BYTES;
    }

    #pragma unroll
    for (int r = 0; r < 4; r++) {
        uint32_t so = (uint32_t)(rowv[r] * RS + segv[r] * 8) * 2;
        cp16(sb + so,              &A[(size_t)(bm + rowv[r]) * K + segv[r] * 8]);
        cp16(sb + BREG_BYTES + so, &W[(size_t)(bn + rowv[r]) * K + segv[r] * 8]);
    }
    asm volatile("cp.async.commit_group;" ::: "memory");

    const int NCH = K / 64;
    #pragma unroll 1
    for (int ch = 0; ch < NCH; ch++) {
        const uint32_t bufB = (uint32_t)(ch & 1) * ABUF_BYTES;
        if (ch + 1 < NCH) {
            const uint32_t nbufB = (uint32_t)((ch + 1) & 1) * ABUF_BYTES;
            const int k0n = (ch + 1) * 64;
            #pragma unroll
            for (int r = 0; r < 4; r++) {
                uint32_t so = (uint32_t)(rowv[r] * RS + segv[r] * 8) * 2;
                cp16(sb + nbufB + so,
                     &A[(size_t)(bm + rowv[r]) * K + k0n + segv[r] * 8]);
                cp16(sb + BREG_BYTES + nbufB + so,
                     &W[(size_t)(bn + rowv[r]) * K + k0n + segv[r] * 8]);
            }
            asm volatile("cp.async.commit_group;" ::: "memory");
            asm volatile("cp.async.wait_group 1;" ::: "memory");
        } else {
            asm volatile("cp.async.wait_group 0;" ::: "memory");
        }
        __syncthreads();

        #pragma unroll
        for (int ks = 0; ks < 4; ks++) {
            const uint32_t kb = sb + bufB + (uint32_t)ks * 32;
            uint32_t a0[4], a1[4];
            ldm_x4(a0, kb + aoffb[0]);
            ldm_x4(a1, kb + aoffb[1]);
            #pragma unroll
            for (int p = 0; p < 4; p++) {
                uint32_t bb[4];
                ldm_x4(bb, kb + boffb[p]);
                mma_fp16(acc[0][2*p],   a0, bb[0], bb[1]);
                mma_fp16(acc[1][2*p],   a1, bb[0], bb[1]);
                mma_fp16(acc[0][2*p+1], a0, bb[2], bb[3]);
                mma_fp16(acc[1][2*p+1], a1, bb[2], bb[3]);
            }
        }
        __syncthreads();
    }

    #pragma unroll
    for (int mt = 0; mt < 2; mt++) {
        #pragma unroll
        for (int nt = 0; nt < 8; nt++) {
            int row = bm + wm + mt * 16 + qrow;
            int col = bn + wn + nt * 8 + qcol * 2;
            #pragma unroll
            for (int half = 0; half < 2; half++) {
                int r = row + half * 8;
                float z0 = acc[mt][nt][half * 2 + 0];
                float z1 = acc[mt][nt][half * 2 + 1];
                if (mode == 0) {
                    float s0 = 1.f / (1.f + __expf(-z0));
                    float s1 = 1.f / (1.f + __expf(-z1));
                    float2 o = make_float2(z0 * s0, z1 * s1);
                    *reinterpret_cast<float2*>(&C[(size_t)r * Nc + col]) = o;
                } else if (mode == 1) {
                    float f0 = 1.f / (1.f + __expf(-z0));
                    float f1 = 1.f / (1.f + __expf(-z1));
                    float2 kk2 = make_float2(1.f - f0, 1.f - f1);
                    float2 gg2 = make_float2(-log1pf(__expf(-f0)),
                                             -log1pf(__expf(-f1)));
                    *reinterpret_cast<float2*>(&C [(size_t)r * Nc + col]) = kk2;
                    *reinterpret_cast<float2*>(&C2[(size_t)r * Nc + col]) = gg2;
                } else {
                    float2 o = make_float2(z0, z1);
                    *reinterpret_cast<float2*>(&C[(size_t)r * Nc + col]) = o;
                }
            }
        }
    }
}

// ---------------------------------------------------------------------------
// Scan role (R13): 256-thr CTA = 2 scan blocks (one per warp-quad),
// __syncwarp only. TCH steps per launch; state carried in g_state.
// ---------------------------------------------------------------------------
__device__ __forceinline__
void scan_role(int cta, int cs,
               const float* __restrict__ Q, const float* __restrict__ Kk,
               const float* __restrict__ G, const float* __restrict__ V,
               float* __restrict__ P0, float* __restrict__ P1,
               float* __restrict__ P2, float* __restrict__ P3,
               float* __restrict__ ST, float* smemf)
{
    float* sq = smemf;
    float* sk = smemf + 512;
    float* se = smemf + 1024;

    const int t = threadIdx.x;
    const int w = t >> 5, lane = t & 31;
    const int o = cta * 2 + (w >> 2);
    const int bh  = o & 31;
    const int dvb = (o >> 5) & 3;
    const int dkb = o >> 7;
    const int b = bh >> 3, h = bh & 7;
    const int owid = w & 3;
    const int dv_local = owid * 8 + (lane >> 2);
    const int dkq = lane & 3;
    const int vcol = dvb * 32 + dv_local;
    const int tid128 = owid * 32 + lane;

    float* OP = (dkb == 0) ? P0 : (dkb == 1) ? P1 : (dkb == 2) ? P2 : P3;

    const size_t base = (size_t)b * NN * DD + (size_t)h * HDIM;

    float S[8];
    if (cs == 0) {
        #pragma unroll
        for (int i = 0; i < 8; i++) S[i] = 0.f;
    } else {
        #pragma unroll
        for (int i = 0; i < 8; i++)
            S[i] = ST[((size_t)o * 128 + tid128) * 8 + i];
    }

    size_t off = base + (size_t)(cs * TCH) * DD;
    float r0 = Q [off + dkb*32 + lane];
    float r1 = Kk[off + dkb*32 + lane];
    float r2 = G [off + dkb*32 + lane];
    float rv = V [off + vcol];

    #pragma unroll 1
    for (int tstep = 0; tstep < TCH; tstep++) {
        const int bi = (tstep & 1) * 256 + w * 32;
        sq[bi + lane] = r0;
        sk[bi + lane] = r1;
        se[bi + lane] = __expf(r2);
        const float vv = rv;

        const size_t noff = off + DD;
        if (tstep + 1 < TCH) {
            r0 = Q [noff + dkb*32 + lane];
            r1 = Kk[noff + dkb*32 + lane];
            r2 = G [noff + dkb*32 + lane];
            rv = V [noff + vcol];
        }
        __syncwarp();

        const float4* q4 = reinterpret_cast<const float4*>(sq + bi);
        const float4* k4 = reinterpret_cast<const float4*>(sk + bi);
        const float4* e4 = reinterpret_cast<const float4*>(se + bi);

        float oacc = 0.f;
        #pragma unroll
        for (int j = 0; j < 2; j++) {
            const int fi = dkq * 2 + j;
            float4 qa = q4[fi], ka = k4[fi], ea = e4[fi];
            float s;
            s = fmaf(ea.x, S[4*j+0], ka.x * vv); S[4*j+0] = s; oacc = fmaf(qa.x, s, oacc);
            s = fmaf(ea.y, S[4*j+1], ka.y * vv); S[4*j+1] = s; oacc = fmaf(qa.y, s, oacc);
            s = fmaf(ea.z, S[4*j+2], ka.z * vv); S[4*j+2] = s; oacc = fmaf(qa.z, s, oacc);
            s = fmaf(ea.w, S[4*j+3], ka.w * vv); S[4*j+3] = s; oacc = fmaf(qa.w, s, oacc);
        }
        oacc += __shfl_xor_sync(0xffffffffu, oacc, 1);
        oacc += __shfl_xor_sync(0xffffffffu, oacc, 2);
        if (dkq == 0) OP[off + vcol] = oacc;

        off = noff;
    }

    if (cs < NCHUNK - 1) {
        #pragma unroll
        for (int i = 0; i < 8; i++)
            ST[((size_t)o * 128 + tid128) * 8 + i] = S[i];
    }
}

// ---------------------------------------------------------------------------
// RMSNorm role (R13): 4 rows per CTA, 4-way partial sum fused, fp16 out.
// ---------------------------------------------------------------------------
__device__ __forceinline__
void rms_role(int cta, int cr,
              const float* __restrict__ X0, const float* __restrict__ X1,
              const float* __restrict__ X2, const float* __restrict__ X3,
              const float* __restrict__ w, __half2* __restrict__ Y,
              float* smemf)
{
    float* red = smemf;
    const int t = threadIdx.x;

    #pragma unroll 1
    for (int r = 0; r < 4; r++) {
        const int ci  = cta * 4 + r;                     // 0..BB*TCH-1
        const int row = (ci >> 8) * NN + cr * TCH + (ci & (TCH - 1));
        const size_t idx = (size_t)row * DD + t * 4;

        float4 a  = *reinterpret_cast<const float4*>(&X0[idx]);
        float4 bq = *reinterpret_cast<const float4*>(&X1[idx]);
        float4 c  = *reinterpret_cast<const float4*>(&X2[idx]);
        float4 d  = *reinterpret_cast<const float4*>(&X3[idx]);
        float4 xv;
        xv.x = (a.x + bq.x) + (c.x + d.x);
        xv.y = (a.y + bq.y) + (c.y + d.y);
        xv.z = (a.z + bq.z) + (c.z + d.z);
        xv.w = (a.w + bq.w) + (c.w + d.w);

        float ss = xv.x*xv.x + xv.y*xv.y + xv.z*xv.z + xv.w*xv.w;
        #pragma unroll
        for (int o = 16; o; o >>= 1) ss += __shfl_xor_sync(0xffffffffu, ss, o);
        if ((t & 31) == 0) red[t >> 5] = ss;
        __syncthreads();
        if (t < 8) {
            float x = red[t];
            #pragma unroll
            for (int o = 4; o; o >>= 1) x += __shfl_xor_sync(0xffu, x, o);
            if (t == 0) red[0] = x;
        }
        __syncthreads();
        float inv = rsqrtf(red[0] * (1.f / DD) + 1e-6f);

        float4 wv = *reinterpret_cast<const float4*>(&w[t * 4]);
        size_t o2 = (size_t)row * (DD/2) + t * 2;
        Y[o2]   = __floats2half2_rn(xv.x * inv * wv.x, xv.y * inv * wv.y);
        Y[o2+1] = __floats2half2_rn(xv.z * inv * wv.z, xv.w * inv * wv.w);
        __syncthreads();
    }
}

// ---------------------------------------------------------------------------
// cvtx role: convert x time-chunk ccv to fp16. 64 CTAs x 256 thr x 16 float4.
// ---------------------------------------------------------------------------
__device__ __forceinline__
void cvtx_role(int cta, int ccv, const float4* __restrict__ x,
               __half2* __restrict__ hx)
{
    int tid = cta * 256 + threadIdx.x;     // 0..16383
    #pragma unroll 1
    for (int it = 0; it < 16; it++) {
        int j = tid + it * 16384;          // 0..N4CH-1
        int b = j >> 16;                   // / N4PB
        int rem = j & (N4PB - 1);
        size_t r = (size_t)b * (NN * DD / 4) + (size_t)ccv * N4PB + rem;
        float4 v = x[r];
        hx[2*r]   = __floats2half2_rn(v.x, v.y);
        hx[2*r+1] = __floats2half2_rn(v.z, v.w);
    }
}

// ---------------------------------------------------------------------------
// Time-chunk GEMM m-tile mapping. TCH=256 => 2 m-tiles per batch per chunk.
// ---------------------------------------------------------------------------
__device__ __forceinline__ int chunk_bm(int c, int mt) {
    return (mt >> 1) * NN + c * TCH + (mt & 1) * 128;
}

// ---------------------------------------------------------------------------
// Mega kernel. R13 ordering (short roles first):
// [scan | rms | cvtx | O-tiles | QKV-tiles]
// O role supports MULTIPLE chunks per launch: chunk = co + (bid>>6).
// ---------------------------------------------------------------------------
__global__ __launch_bounds__(256, 2)
void mega_kernel(const float4* __restrict__ xf, const __half* __restrict__ hx,
                 const __half* __restrict__ hw,
                 float* __restrict__ pq, float* __restrict__ pk,
                 float* __restrict__ pg, float* __restrict__ pv,
                 float* __restrict__ p0, float* __restrict__ p1,
                 float* __restrict__ p2, float* __restrict__ p3,
                 float* __restrict__ pstate, __half* __restrict__ hnrm,
                 const float* __restrict__ norm_w, float* __restrict__ outp,
                 int n_scan, int cs, int n_rms, int cr, int n_cvt, int ccv,
                 int n_o, int co, int n_qkv, int cq)
{
    extern __shared__ __align__(16) __half smem_raw[];
    int bid = blockIdx.x;

    if (bid < n_scan) {
        scan_role(bid, cs, pq, pk, pg, pv, p0, p1, p2, p3, pstate,
                  reinterpret_cast<float*>(smem_raw));
        return;
    }
    bid -= n_scan;
    if (bid < n_rms) {
        rms_role(bid, cr, p0, p1, p2, p3, norm_w,
                 reinterpret_cast<__half2*>(hnrm),
                 reinterpret_cast<float*>(smem_raw));
        return;
    }
    bid -= n_rms;
    if (bid < n_cvt) {
        cvtx_role(bid, ccv, xf, (__half2*)hx);
        return;
    }
    bid -= n_cvt;
    const uint32_t sb = s2u(smem_raw);
    if (bid < n_o) {
        int oc   = co + (bid >> 6);          // chunk (supports n_o = 64 or 128)
        int tile = bid & 63;
        int mt = tile >> 3, nt = tile & 7;
        gemm_tile(hnrm, hw + 3*(size_t)DD*DD, outp, nullptr,
                  chunk_bm(oc, mt), nt * 128, 2, sb);
        return;
    }
    bid -= n_o;
    // QKV tiles: 192 per chunk (3 GEMMs x 8 m-tiles x 8 n-tiles)
    int which = bid >> 6;
    int tile  = bid & 63;
    int mt = tile >> 3, nt = tile & 7;
    const __half* Wp = hw + (size_t)which * DD * DD;
    float* C  = (which == 0) ? pq : (which == 1) ? pk : pv;
    float* C2 = (which == 1) ? pg : nullptr;
    gemm_tile(hx, Wp, C, C2, chunk_bm(cq, mt), nt * 128, which, sb);
}

// ---------------------------------------------------------------------------
extern "C" void kernel_launch(void* const* d_in, const int* in_sizes, int n_in,
                              void* d_out, int out_size)
{
    const float* x      = (const float*)d_in[0];
    const float* Wq     = (const float*)d_in[1];
    const float* Wk     = (const float*)d_in[2];
    const float* Wv     = (const float*)d_in[3];
    const float* Wo     = (const float*)d_in[4];
    const float* norm_w = (const float*)d_in[5];
    float* out = (float*)d_out;

    float *pq, *pk, *pg, *pv, *p0, *p1, *p2, *p3, *pstate;
    __half *phx, *phw, *phnrm;
    cudaGetSymbolAddress((void**)&pq,     g_q);
    cudaGetSymbolAddress((void**)&pk,     g_k);
    cudaGetSymbolAddress((void**)&pg,     g_g);
    cudaGetSymbolAddress((void**)&pv,     g_v);
    cudaGetSymbolAddress((void**)&p0,     g_p0);
    cudaGetSymbolAddress((void**)&p1,     g_p1);
    cudaGetSymbolAddress((void**)&p2,     g_p2);
    cudaGetSymbolAddress((void**)&p3,     g_p3);
    cudaGetSymbolAddress((void**)&pstate, g_state);
    cudaGetSymbolAddress((void**)&phx,    g_hx);
    cudaGetSymbolAddress((void**)&phw,    g_hw);
    cudaGetSymbolAddress((void**)&phnrm,  g_hnrm);

    // L0: convert the 4 weights + x time-chunk 0 (~8 us)
    const int n0 = 4 * N4W + N4CH;
    cvt0_kernel<<<(n0 + 255) / 256, 256>>>(
        (const float4*)x, (const float4*)Wq, (const float4*)Wk,
        (const float4*)Wv, (const float4*)Wo,
        (__half2*)phx, (__half2*)phw);

    cudaFuncSetAttribute(mega_kernel,
        cudaFuncAttributeMaxDynamicSharedMemorySize, GEMM_SMEM_BYTES);

    #define LAUNCH(nsc, csv, nrm, crv, ncv, ccv, no, cov, nqkv, cqv)             \
        mega_kernel<<<(nsc)+(nrm)+(ncv)+(no)+(nqkv), 256, GEMM_SMEM_BYTES>>>(    \
            (const float4*)x, phx, phw, pq, pk, pg, pv, p0, p1, p2, p3,          \
            pstate, phnrm, norm_w, out,                                          \
            (nsc), (csv), (nrm), (crv), (ncv), (ccv), (no), (cov), (nqkv), (cqv))

    // 8-chunk pipeline (R13 ordering: short roles first); cvtx(k) one launch
    // ahead of QKV(k). Roles: scan=256, rms=256, cvtx=64, O=64/128, QKV=192.
    LAUNCH(  0, 0,   0, 0, 64, 1,   0, 0, 192, 0);   //                cvtx(1) QKV(0)
    LAUNCH(256, 0,   0, 0, 64, 2,   0, 0, 192, 1);   // scan(0)        cvtx(2) QKV(1)
    LAUNCH(256, 1, 256, 0, 64, 3,   0, 0, 192, 2);   // scan(1) rms(0) cvtx(3) QKV(2)
    LAUNCH(256, 2, 256, 1, 64, 4,  64, 0, 192, 3);   // + O(0)
    LAUNCH(256, 3, 256, 2, 64, 5,  64, 1, 192, 4);
    LAUNCH(256, 4, 256, 3, 64, 6,  64, 2, 192, 5);
    LAUNCH(256, 5, 256, 4, 64, 7,  64, 3, 192, 6);
    LAUNCH(256, 6, 256, 5,  0, 0,  64, 4, 192, 7);
    // Drain (compressed): O(5) and O(6) share one launch once rms(6) is done.
    LAUNCH(256, 7, 256, 6,  0, 0,   0, 0,   0, 0);   // scan(7) rms(6)
    LAUNCH(  0, 0, 256, 7,  0, 0, 128, 5,   0, 0);   // rms(7) O(5)+O(6)
    LAUNCH(  0, 0,   0, 0,  0, 0,  64, 7,   0, 0);   //        O(7)
    #undef LAUNCH
}